// round 12
// baseline (speedup 1.0000x reference)
#include <cuda_runtime.h>
#include <cuda_bf16.h>

#define H  100000
#define E  200000
#define NI 1000000
#define CAP 64
#define NB_BUILD 1563   // builder blocks fused at the front of k_edge_mlp's grid

typedef unsigned long long u64;

// ---------------- scratch (device globals: no allocations allowed) ----------
__device__ int    g_e_cnt[E];
__device__ int    g_n_cnt[H];
__device__ int    g_e_list[E * CAP];    // node ids per edge
__device__ int    g_n_list[H * CAP];    // edge ids per node
__device__ float4 g_edge_mean[E * 32];  // [E][128]
__device__ float4 g_edge_msg[E * 32];   // [E][128]

// transposed weights: [k][out] so the k-loop load is lane-coalesced float4
__device__ float4 g_W1t[192 * 32];      // from We1 [128][192]
__device__ float4 g_W2t[128 * 32];      // from We2 [128][128]
__device__ float4 g_Wpt[128 * 32];      // from Wp
__device__ float4 g_Wn1t[128 * 32];
__device__ float4 g_Wn2t[128 * 32];

// ---------------- packed f32x2 helpers ---------------------------------------
__device__ __forceinline__ u64 ffma2(u64 a, u64 b, u64 c) {
    u64 d; asm("fma.rn.f32x2 %0, %1, %2, %3;" : "=l"(d) : "l"(a), "l"(b), "l"(c)); return d;
}
__device__ __forceinline__ u64 add2(u64 a, u64 b) {
    u64 d; asm("add.rn.f32x2 %0, %1, %2;" : "=l"(d) : "l"(a), "l"(b)); return d;
}
__device__ __forceinline__ u64 mul2(u64 a, u64 b) {
    u64 d; asm("mul.rn.f32x2 %0, %1, %2;" : "=l"(d) : "l"(a), "l"(b)); return d;
}
__device__ __forceinline__ u64 dup2(float f) {
    u64 d; asm("mov.b64 %0, {%1, %1};" : "=l"(d) : "f"(f)); return d;
}
__device__ __forceinline__ u64 pack2(float x, float y) {
    u64 d; asm("mov.b64 %0, {%1, %2};" : "=l"(d) : "f"(x), "f"(y)); return d;
}
__device__ __forceinline__ float2 unpack2(u64 v) {
    float2 r; asm("mov.b64 {%0, %1}, %2;" : "=f"(r.x), "=f"(r.y) : "l"(v)); return r;
}

// ---------------- prep: zero counters + transpose weights --------------------
__global__ void k_prep_zero(const float* __restrict__ We1, const float* __restrict__ We2,
                            const float* __restrict__ Wp,  const float* __restrict__ Wn1,
                            const float* __restrict__ Wn2) {
    int i = blockIdx.x * blockDim.x + threadIdx.x;
    if (i < E) g_e_cnt[i] = 0;
    if (i < H) g_n_cnt[i] = 0;
    if (i < 192 * 128) {
        int k = i / 128, o = i % 128;
        ((float*)g_W1t)[i] = We1[o * 192 + k];
    }
    if (i < 128 * 128) {
        int k = i / 128, o = i % 128;
        ((float*)g_W2t)[i]  = We2[o * 128 + k];
        ((float*)g_Wpt)[i]  = Wp [o * 128 + k];
        ((float*)g_Wn1t)[i] = Wn1[o * 128 + k];
        ((float*)g_Wn2t)[i] = Wn2[o * 128 + k];
    }
}

// ---------------- build edge-side lists (4 incidences / thread) ---------------
__global__ void __launch_bounds__(256) k_build_e(const int* __restrict__ fg,
                                                 const int* __restrict__ res) {
    int i = blockIdx.x * blockDim.x + threadIdx.x;
    if (i >= NI / 4) return;
    int4 f = ((const int4*)fg)[i];
    int4 r = ((const int4*)res)[i];
    int s;
    s = atomicAdd(&g_e_cnt[r.x], 1); if (s < CAP) g_e_list[r.x * CAP + s] = f.x;
    s = atomicAdd(&g_e_cnt[r.y], 1); if (s < CAP) g_e_list[r.y * CAP + s] = f.y;
    s = atomicAdd(&g_e_cnt[r.z], 1); if (s < CAP) g_e_list[r.z * CAP + s] = f.z;
    s = atomicAdd(&g_e_cnt[r.w], 1); if (s < CAP) g_e_list[r.w * CAP + s] = f.w;
}

// ---------------- gather-mean node -> edge (warp per edge) --------------------
__global__ void __launch_bounds__(256) k_gather_edge(const float4* __restrict__ xh) {
    int w = (blockIdx.x * blockDim.x + threadIdx.x) >> 5;   // edge id, grid exact
    int lane = threadIdx.x & 31;
    int cnt = min(g_e_cnt[w], CAP);
    float4 acc = make_float4(0.f, 0.f, 0.f, 0.f);
    const int* lst = &g_e_list[w * CAP];
    int m = 0;
    for (; m + 4 <= cnt; m += 4) {
        int4 id = *(const int4*)(lst + m);
        float4 v0 = xh[id.x * 32 + lane];
        float4 v1 = xh[id.y * 32 + lane];
        float4 v2 = xh[id.z * 32 + lane];
        float4 v3 = xh[id.w * 32 + lane];
        acc.x += (v0.x + v1.x) + (v2.x + v3.x);
        acc.y += (v0.y + v1.y) + (v2.y + v3.y);
        acc.z += (v0.z + v1.z) + (v2.z + v3.z);
        acc.w += (v0.w + v1.w) + (v2.w + v3.w);
    }
    for (; m < cnt; m++) {
        int id = lst[m];
        float4 v = xh[id * 32 + lane];
        acc.x += v.x; acc.y += v.y; acc.z += v.z; acc.w += v.w;
    }
    float inv = 1.f / (float)max(cnt, 1);
    g_edge_mean[w * 32 + lane] = make_float4(acc.x * inv, acc.y * inv, acc.z * inv, acc.w * inv);
}

// =============================================================================
// Edge MLP (+ fused node-side list build).
// Blocks [0, NB_BUILD): build g_n_list (runs concurrently under MLP FMA shadow).
// Blocks [NB_BUILD, NB_BUILD+5000): 5 warps, 8 edges/warp as 4 pairs, FFMA2.
// smem rows are 32B (4 pairs, NO pad): main-loop reads are warp-broadcast
// (conflict-free at any stride); only amortized staging stores pay conflicts.
// 30.7KB/block -> ~7 blocks/SM (occupancy ~55% vs 28.6% with padded rows).
// =============================================================================
__global__ void __launch_bounds__(160) k_edge_mlp(const float4* __restrict__ attr,
                                                  const float* __restrict__ be1,
                                                  const float* __restrict__ be2,
                                                  const int* __restrict__ fg,
                                                  const int* __restrict__ res) {
    if (blockIdx.x < NB_BUILD) {
        // ---- builder path: node-side lists, 4 incidences / thread ----
        int t = blockIdx.x * 160 + threadIdx.x;
        int base = t * 4;
        if (base + 4 <= NI) {
            int4 f = *(const int4*)(fg + base);
            int4 r = *(const int4*)(res + base);
            int s;
            s = atomicAdd(&g_n_cnt[f.x], 1); if (s < CAP) g_n_list[f.x * CAP + s] = r.x;
            s = atomicAdd(&g_n_cnt[f.y], 1); if (s < CAP) g_n_list[f.y * CAP + s] = r.y;
            s = atomicAdd(&g_n_cnt[f.z], 1); if (s < CAP) g_n_list[f.z * CAP + s] = r.z;
            s = atomicAdd(&g_n_cnt[f.w], 1); if (s < CAP) g_n_list[f.w * CAP + s] = r.w;
        } else {
            for (int i = base; i < NI; i++) {
                int f = fg[i], r = res[i];
                int s = atomicAdd(&g_n_cnt[f], 1);
                if (s < CAP) g_n_list[f * CAP + s] = r;
            }
        }
        return;
    }

    __shared__ __align__(16) float2 s[5][192][4];   // 30720 B
    int warp = threadIdx.x >> 5, lane = threadIdx.x & 31;
    int e0 = ((blockIdx.x - NB_BUILD) * 5 + warp) * 8;

    // ---- stage e_in pairs: mean rows k=0..127 (G=48), attr rows k=128..191 ----
    #pragma unroll
    for (int jp = 0; jp < 4; jp++) {
        int ea = e0 + 2 * jp, eb = ea + 1;
        float4 a0 = g_edge_mean[ea * 32 + lane];
        float4 a1 = g_edge_mean[eb * 32 + lane];
        s[warp][0 * 48 + lane][jp] = make_float2(a0.x, a1.x);
        s[warp][1 * 48 + lane][jp] = make_float2(a0.y, a1.y);
        s[warp][2 * 48 + lane][jp] = make_float2(a0.z, a1.z);
        s[warp][3 * 48 + lane][jp] = make_float2(a0.w, a1.w);
        if (lane < 16) {
            float4 t0 = attr[ea * 16 + lane];
            float4 t1 = attr[eb * 16 + lane];
            s[warp][0 * 48 + 32 + lane][jp] = make_float2(t0.x, t1.x);
            s[warp][1 * 48 + 32 + lane][jp] = make_float2(t0.y, t1.y);
            s[warp][2 * 48 + 32 + lane][jp] = make_float2(t0.z, t1.z);
            s[warp][3 * 48 + 32 + lane][jp] = make_float2(t0.w, t1.w);
        }
    }
    __syncwarp();

    // ---- GEMM1: [8 x 192] @ [192 x 128] + bias, relu ----
    u64 acc[4][4];
    {
        float4 b = ((const float4*)be1)[lane];
        u64 b0 = dup2(b.x), b1 = dup2(b.y), b2 = dup2(b.z), b3 = dup2(b.w);
        #pragma unroll
        for (int jp = 0; jp < 4; jp++) {
            acc[0][jp] = b0; acc[1][jp] = b1; acc[2][jp] = b2; acc[3][jp] = b3;
        }
    }
    #pragma unroll 2
    for (int kb = 0; kb < 48; kb++) {
        #pragma unroll
        for (int c = 0; c < 4; c++) {
            float4 w = g_W1t[(kb * 4 + c) * 32 + lane];
            u64 w0 = dup2(w.x), w1 = dup2(w.y), w2 = dup2(w.z), w3 = dup2(w.w);
            const float2* row = s[warp][c * 48 + kb];
            ulonglong2 pA = *(const ulonglong2*)(row);       // jp0, jp1
            ulonglong2 pB = *(const ulonglong2*)(row + 2);   // jp2, jp3
            acc[0][0] = ffma2(w0, pA.x, acc[0][0]); acc[1][0] = ffma2(w1, pA.x, acc[1][0]);
            acc[2][0] = ffma2(w2, pA.x, acc[2][0]); acc[3][0] = ffma2(w3, pA.x, acc[3][0]);
            acc[0][1] = ffma2(w0, pA.y, acc[0][1]); acc[1][1] = ffma2(w1, pA.y, acc[1][1]);
            acc[2][1] = ffma2(w2, pA.y, acc[2][1]); acc[3][1] = ffma2(w3, pA.y, acc[3][1]);
            acc[0][2] = ffma2(w0, pB.x, acc[0][2]); acc[1][2] = ffma2(w1, pB.x, acc[1][2]);
            acc[2][2] = ffma2(w2, pB.x, acc[2][2]); acc[3][2] = ffma2(w3, pB.x, acc[3][2]);
            acc[0][3] = ffma2(w0, pB.y, acc[0][3]); acc[1][3] = ffma2(w1, pB.y, acc[1][3]);
            acc[2][3] = ffma2(w2, pB.y, acc[2][3]); acc[3][3] = ffma2(w3, pB.y, acc[3][3]);
        }
    }
    __syncwarp();

    // ---- relu + restage hidden (rows 0..127, G=32) ----
    #pragma unroll
    for (int i = 0; i < 4; i++)
        #pragma unroll
        for (int jp = 0; jp < 4; jp++) {
            float2 v = unpack2(acc[i][jp]);
            s[warp][i * 32 + lane][jp] = make_float2(fmaxf(v.x, 0.f), fmaxf(v.y, 0.f));
        }
    __syncwarp();

    // ---- GEMM2: [8 x 128] @ [128 x 128] + bias ----
    {
        float4 b = ((const float4*)be2)[lane];
        u64 b0 = dup2(b.x), b1 = dup2(b.y), b2 = dup2(b.z), b3 = dup2(b.w);
        #pragma unroll
        for (int jp = 0; jp < 4; jp++) {
            acc[0][jp] = b0; acc[1][jp] = b1; acc[2][jp] = b2; acc[3][jp] = b3;
        }
    }
    #pragma unroll 2
    for (int kb = 0; kb < 32; kb++) {
        #pragma unroll
        for (int c = 0; c < 4; c++) {
            float4 w = g_W2t[(kb * 4 + c) * 32 + lane];
            u64 w0 = dup2(w.x), w1 = dup2(w.y), w2 = dup2(w.z), w3 = dup2(w.w);
            const float2* row = s[warp][c * 32 + kb];
            ulonglong2 pA = *(const ulonglong2*)(row);
            ulonglong2 pB = *(const ulonglong2*)(row + 2);
            acc[0][0] = ffma2(w0, pA.x, acc[0][0]); acc[1][0] = ffma2(w1, pA.x, acc[1][0]);
            acc[2][0] = ffma2(w2, pA.x, acc[2][0]); acc[3][0] = ffma2(w3, pA.x, acc[3][0]);
            acc[0][1] = ffma2(w0, pA.y, acc[0][1]); acc[1][1] = ffma2(w1, pA.y, acc[1][1]);
            acc[2][1] = ffma2(w2, pA.y, acc[2][1]); acc[3][1] = ffma2(w3, pA.y, acc[3][1]);
            acc[0][2] = ffma2(w0, pB.x, acc[0][2]); acc[1][2] = ffma2(w1, pB.x, acc[1][2]);
            acc[2][2] = ffma2(w2, pB.x, acc[2][2]); acc[3][2] = ffma2(w3, pB.x, acc[3][2]);
            acc[0][3] = ffma2(w0, pB.y, acc[0][3]); acc[1][3] = ffma2(w1, pB.y, acc[1][3]);
            acc[2][3] = ffma2(w2, pB.y, acc[2][3]); acc[3][3] = ffma2(w3, pB.y, acc[3][3]);
        }
    }

    // ---- write both edges of each pair ----
    #pragma unroll
    for (int jp = 0; jp < 4; jp++) {
        float2 v0 = unpack2(acc[0][jp]), v1 = unpack2(acc[1][jp]);
        float2 v2 = unpack2(acc[2][jp]), v3 = unpack2(acc[3][jp]);
        g_edge_msg[(e0 + 2 * jp)     * 32 + lane] = make_float4(v0.x, v1.x, v2.x, v3.x);
        g_edge_msg[(e0 + 2 * jp + 1) * 32 + lane] = make_float4(v0.y, v1.y, v2.y, v3.y);
    }
}

// =============================================================================
// Node: fused gather-mean prologue + MLP + residual + relu + layernorm.
// 8 warps/block, 8 nodes/warp (4 pairs). 32KB smem (unpadded rows).
// =============================================================================
__global__ void __launch_bounds__(256) k_node(const float4* __restrict__ xh,
                                              const float* __restrict__ bp,
                                              const float* __restrict__ bn1,
                                              const float* __restrict__ bn2,
                                              const float4* __restrict__ gamma4,
                                              const float4* __restrict__ beta4,
                                              float4* __restrict__ out) {
    __shared__ __align__(16) float2 s[8][128][4];   // 32768 B
    int warp = threadIdx.x >> 5, lane = threadIdx.x & 31;
    int wg = blockIdx.x * 8 + warp;
    if (wg >= (H / 8)) return;                      // H = 12500 * 8
    int n0 = wg * 8;

    // ---- gather node means directly into smem pair slots ----
    #pragma unroll
    for (int jp = 0; jp < 4; jp++) {
        float4 mean[2];
        #pragma unroll
        for (int half = 0; half < 2; half++) {
            int n = n0 + 2 * jp + half;
            int cnt = min(g_n_cnt[n], CAP);
            const int* lst = &g_n_list[n * CAP];
            float4 acc = make_float4(0.f, 0.f, 0.f, 0.f);
            int m = 0;
            for (; m + 4 <= cnt; m += 4) {
                int4 id = *(const int4*)(lst + m);
                float4 v0 = g_edge_msg[id.x * 32 + lane];
                float4 v1 = g_edge_msg[id.y * 32 + lane];
                float4 v2 = g_edge_msg[id.z * 32 + lane];
                float4 v3 = g_edge_msg[id.w * 32 + lane];
                acc.x += (v0.x + v1.x) + (v2.x + v3.x);
                acc.y += (v0.y + v1.y) + (v2.y + v3.y);
                acc.z += (v0.z + v1.z) + (v2.z + v3.z);
                acc.w += (v0.w + v1.w) + (v2.w + v3.w);
            }
            for (; m < cnt; m++) {
                int id = lst[m];
                float4 v = g_edge_msg[id * 32 + lane];
                acc.x += v.x; acc.y += v.y; acc.z += v.z; acc.w += v.w;
            }
            float inv = 1.f / (float)max(cnt, 1);
            mean[half] = make_float4(acc.x * inv, acc.y * inv, acc.z * inv, acc.w * inv);
        }
        s[warp][0 * 32 + lane][jp] = make_float2(mean[0].x, mean[1].x);
        s[warp][1 * 32 + lane][jp] = make_float2(mean[0].y, mean[1].y);
        s[warp][2 * 32 + lane][jp] = make_float2(mean[0].z, mean[1].z);
        s[warp][3 * 32 + lane][jp] = make_float2(mean[0].w, mean[1].w);
    }
    __syncwarp();

    // ---- t = relu(Wn1 @ m + bn1) ----
    u64 a[4][4];
    {
        float4 b = ((const float4*)bn1)[lane];
        u64 b0 = dup2(b.x), b1 = dup2(b.y), b2 = dup2(b.z), b3 = dup2(b.w);
        #pragma unroll
        for (int jp = 0; jp < 4; jp++) {
            a[0][jp] = b0; a[1][jp] = b1; a[2][jp] = b2; a[3][jp] = b3;
        }
    }
    #pragma unroll 2
    for (int kb = 0; kb < 32; kb++) {
        #pragma unroll
        for (int c = 0; c < 4; c++) {
            float4 w = g_Wn1t[(kb * 4 + c) * 32 + lane];
            u64 w0 = dup2(w.x), w1 = dup2(w.y), w2 = dup2(w.z), w3 = dup2(w.w);
            const float2* row = s[warp][c * 32 + kb];
            ulonglong2 pA = *(const ulonglong2*)(row);
            ulonglong2 pB = *(const ulonglong2*)(row + 2);
            a[0][0] = ffma2(w0, pA.x, a[0][0]); a[1][0] = ffma2(w1, pA.x, a[1][0]);
            a[2][0] = ffma2(w2, pA.x, a[2][0]); a[3][0] = ffma2(w3, pA.x, a[3][0]);
            a[0][1] = ffma2(w0, pA.y, a[0][1]); a[1][1] = ffma2(w1, pA.y, a[1][1]);
            a[2][1] = ffma2(w2, pA.y, a[2][1]); a[3][1] = ffma2(w3, pA.y, a[3][1]);
            a[0][2] = ffma2(w0, pB.x, a[0][2]); a[1][2] = ffma2(w1, pB.x, a[1][2]);
            a[2][2] = ffma2(w2, pB.x, a[2][2]); a[3][2] = ffma2(w3, pB.x, a[3][2]);
            a[0][3] = ffma2(w0, pB.y, a[0][3]); a[1][3] = ffma2(w1, pB.y, a[1][3]);
            a[2][3] = ffma2(w2, pB.y, a[2][3]); a[3][3] = ffma2(w3, pB.y, a[3][3]);
        }
    }
    __syncwarp();
    #pragma unroll
    for (int i = 0; i < 4; i++)
        #pragma unroll
        for (int jp = 0; jp < 4; jp++) {
            float2 v = unpack2(a[i][jp]);
            s[warp][i * 32 + lane][jp] = make_float2(fmaxf(v.x, 0.f), fmaxf(v.y, 0.f));
        }
    __syncwarp();

    // ---- acc = Wn2 @ t + (bn2 + bp) ----
    u64 p[4][4];
    {
        float4 b2 = ((const float4*)bn2)[lane];
        float4 bq = ((const float4*)bp)[lane];
        u64 b0 = dup2(b2.x + bq.x), b1 = dup2(b2.y + bq.y);
        u64 b2d = dup2(b2.z + bq.z), b3 = dup2(b2.w + bq.w);
        #pragma unroll
        for (int jp = 0; jp < 4; jp++) {
            p[0][jp] = b0; p[1][jp] = b1; p[2][jp] = b2d; p[3][jp] = b3;
        }
    }
    #pragma unroll 2
    for (int kb = 0; kb < 32; kb++) {
        #pragma unroll
        for (int c = 0; c < 4; c++) {
            float4 w = g_Wn2t[(kb * 4 + c) * 32 + lane];
            u64 w0 = dup2(w.x), w1 = dup2(w.y), w2 = dup2(w.z), w3 = dup2(w.w);
            const float2* row = s[warp][c * 32 + kb];
            ulonglong2 pA = *(const ulonglong2*)(row);
            ulonglong2 pB = *(const ulonglong2*)(row + 2);
            p[0][0] = ffma2(w0, pA.x, p[0][0]); p[1][0] = ffma2(w1, pA.x, p[1][0]);
            p[2][0] = ffma2(w2, pA.x, p[2][0]); p[3][0] = ffma2(w3, pA.x, p[3][0]);
            p[0][1] = ffma2(w0, pA.y, p[0][1]); p[1][1] = ffma2(w1, pA.y, p[1][1]);
            p[2][1] = ffma2(w2, pA.y, p[2][1]); p[3][1] = ffma2(w3, pA.y, p[3][1]);
            p[0][2] = ffma2(w0, pB.x, p[0][2]); p[1][2] = ffma2(w1, pB.x, p[1][2]);
            p[2][2] = ffma2(w2, pB.x, p[2][2]); p[3][2] = ffma2(w3, pB.x, p[3][2]);
            p[0][3] = ffma2(w0, pB.y, p[0][3]); p[1][3] = ffma2(w1, pB.y, p[1][3]);
            p[2][3] = ffma2(w2, pB.y, p[2][3]); p[3][3] = ffma2(w3, pB.y, p[3][3]);
        }
    }
    __syncwarp();

    // ---- stage x pairs, accumulate Wp @ x into p ----
    #pragma unroll
    for (int jp = 0; jp < 4; jp++) {
        int na = n0 + 2 * jp, nb = na + 1;
        float4 a0 = xh[na * 32 + lane];
        float4 a1 = xh[nb * 32 + lane];
        s[warp][0 * 32 + lane][jp] = make_float2(a0.x, a1.x);
        s[warp][1 * 32 + lane][jp] = make_float2(a0.y, a1.y);
        s[warp][2 * 32 + lane][jp] = make_float2(a0.z, a1.z);
        s[warp][3 * 32 + lane][jp] = make_float2(a0.w, a1.w);
    }
    __syncwarp();
    #pragma unroll 2
    for (int kb = 0; kb < 32; kb++) {
        #pragma unroll
        for (int c = 0; c < 4; c++) {
            float4 w = g_Wpt[(kb * 4 + c) * 32 + lane];
            u64 w0 = dup2(w.x), w1 = dup2(w.y), w2 = dup2(w.z), w3 = dup2(w.w);
            const float2* row = s[warp][c * 32 + kb];
            ulonglong2 pA = *(const ulonglong2*)(row);
            ulonglong2 pB = *(const ulonglong2*)(row + 2);
            p[0][0] = ffma2(w0, pA.x, p[0][0]); p[1][0] = ffma2(w1, pA.x, p[1][0]);
            p[2][0] = ffma2(w2, pA.x, p[2][0]); p[3][0] = ffma2(w3, pA.x, p[3][0]);
            p[0][1] = ffma2(w0, pA.y, p[0][1]); p[1][1] = ffma2(w1, pA.y, p[1][1]);
            p[2][1] = ffma2(w2, pA.y, p[2][1]); p[3][1] = ffma2(w3, pA.y, p[3][1]);
            p[0][2] = ffma2(w0, pB.x, p[0][2]); p[1][2] = ffma2(w1, pB.x, p[1][2]);
            p[2][2] = ffma2(w2, pB.x, p[2][2]); p[3][2] = ffma2(w3, pB.x, p[3][2]);
            p[0][3] = ffma2(w0, pB.y, p[0][3]); p[1][3] = ffma2(w1, pB.y, p[1][3]);
            p[2][3] = ffma2(w2, pB.y, p[2][3]); p[3][3] = ffma2(w3, pB.y, p[3][3]);
        }
    }

    // ---- z = relu(p); layernorm per row (paired, 64-bit shuffles) ----
    float4 gm = gamma4[lane], bt = beta4[lane];
    #pragma unroll
    for (int jp = 0; jp < 4; jp++) {
        u64 z[4];
        #pragma unroll
        for (int i = 0; i < 4; i++) {
            float2 v = unpack2(p[i][jp]);
            z[i] = pack2(fmaxf(v.x, 0.f), fmaxf(v.y, 0.f));
        }
        u64 su = add2(add2(z[0], z[1]), add2(z[2], z[3]));
        u64 qu = ffma2(z[0], z[0], ffma2(z[1], z[1], ffma2(z[2], z[2], mul2(z[3], z[3]))));
        #pragma unroll
        for (int o = 16; o > 0; o >>= 1) {
            su = add2(su, __shfl_xor_sync(0xFFFFFFFFu, su, o));
            qu = add2(qu, __shfl_xor_sync(0xFFFFFFFFu, qu, o));
        }
        float2 sm = unpack2(su), qm = unpack2(qu);
        float mu0 = sm.x * (1.f / 128.f), mu1 = sm.y * (1.f / 128.f);
        float r0 = rsqrtf(qm.x * (1.f / 128.f) - mu0 * mu0 + 1e-5f);
        float r1 = rsqrtf(qm.y * (1.f / 128.f) - mu1 * mu1 + 1e-5f);
        float2 c0 = unpack2(z[0]), c1 = unpack2(z[1]), c2 = unpack2(z[2]), c3 = unpack2(z[3]);
        out[(n0 + 2 * jp) * 32 + lane] =
            make_float4((c0.x - mu0) * r0 * gm.x + bt.x, (c1.x - mu0) * r0 * gm.y + bt.y,
                        (c2.x - mu0) * r0 * gm.z + bt.z, (c3.x - mu0) * r0 * gm.w + bt.w);
        out[(n0 + 2 * jp + 1) * 32 + lane] =
            make_float4((c0.y - mu1) * r1 * gm.x + bt.x, (c1.y - mu1) * r1 * gm.y + bt.y,
                        (c2.y - mu1) * r1 * gm.z + bt.z, (c3.y - mu1) * r1 * gm.w + bt.w);
    }
}

// ---------------- launch -----------------------------------------------------
extern "C" void kernel_launch(void* const* d_in, const int* in_sizes, int n_in,
                              void* d_out, int out_size) {
    const float* x_h   = (const float*)d_in[0];
    const float* attr  = (const float*)d_in[1];
    const float* Wp    = (const float*)d_in[2];
    const float* bp    = (const float*)d_in[3];
    const float* We1   = (const float*)d_in[4];
    const float* be1   = (const float*)d_in[5];
    const float* We2   = (const float*)d_in[6];
    const float* be2   = (const float*)d_in[7];
    const float* Wn1   = (const float*)d_in[8];
    const float* bn1   = (const float*)d_in[9];
    const float* Wn2   = (const float*)d_in[10];
    const float* bn2   = (const float*)d_in[11];
    const float* gamma = (const float*)d_in[12];
    const float* beta  = (const float*)d_in[13];
    const int*   fg    = (const int*)d_in[14];
    const int*   res   = (const int*)d_in[15];

    k_prep_zero<<<(E + 255) / 256, 256>>>(We1, We2, Wp, Wn1, Wn2);
    k_build_e<<<(NI / 4 + 255) / 256, 256>>>(fg, res);
    k_gather_edge<<<E / 8, 256>>>((const float4*)x_h);             // 25000 blocks
    k_edge_mlp<<<NB_BUILD + 5000, 160>>>((const float4*)attr, be1, be2, fg, res);
    k_node<<<1563, 256>>>((const float4*)x_h, bp, bn1, bn2,
                          (const float4*)gamma, (const float4*)beta,
                          (float4*)d_out);
}

// round 13
// speedup vs baseline: 1.0924x; 1.0924x over previous
#include <cuda_runtime.h>
#include <cuda_bf16.h>

#define H  100000
#define E  200000
#define NI 1000000
#define CAP 64
#define NB_BUILD 1563   // builder blocks fused at the front of k_edge_mlp's grid

typedef unsigned long long u64;

// ---------------- scratch (device globals: no allocations allowed) ----------
__device__ int    g_e_cnt[E];
__device__ int    g_n_cnt[H];
__device__ int    g_e_list[E * CAP];    // node ids per edge
__device__ int    g_n_list[H * CAP];    // edge ids per node
__device__ float4 g_edge_msg[E * 32];   // [E][128]

// transposed weights: [k][out] so the k-loop load is lane-coalesced float4
__device__ float4 g_W1t[192 * 32];      // from We1 [128][192]
__device__ float4 g_W2t[128 * 32];      // from We2 [128][128]
__device__ float4 g_Wpt[128 * 32];      // from Wp
__device__ float4 g_Wn1t[128 * 32];
__device__ float4 g_Wn2t[128 * 32];

// ---------------- packed f32x2 helpers ---------------------------------------
__device__ __forceinline__ u64 ffma2(u64 a, u64 b, u64 c) {
    u64 d; asm("fma.rn.f32x2 %0, %1, %2, %3;" : "=l"(d) : "l"(a), "l"(b), "l"(c)); return d;
}
__device__ __forceinline__ u64 add2(u64 a, u64 b) {
    u64 d; asm("add.rn.f32x2 %0, %1, %2;" : "=l"(d) : "l"(a), "l"(b)); return d;
}
__device__ __forceinline__ u64 mul2(u64 a, u64 b) {
    u64 d; asm("mul.rn.f32x2 %0, %1, %2;" : "=l"(d) : "l"(a), "l"(b)); return d;
}
__device__ __forceinline__ u64 dup2(float f) {
    u64 d; asm("mov.b64 %0, {%1, %1};" : "=l"(d) : "f"(f)); return d;
}
__device__ __forceinline__ u64 pack2(float x, float y) {
    u64 d; asm("mov.b64 %0, {%1, %2};" : "=l"(d) : "f"(x), "f"(y)); return d;
}
__device__ __forceinline__ float2 unpack2(u64 v) {
    float2 r; asm("mov.b64 {%0, %1}, %2;" : "=f"(r.x), "=f"(r.y) : "l"(v)); return r;
}

// ---------------- prep: zero counters + transpose weights --------------------
__global__ void k_prep_zero(const float* __restrict__ We1, const float* __restrict__ We2,
                            const float* __restrict__ Wp,  const float* __restrict__ Wn1,
                            const float* __restrict__ Wn2) {
    int i = blockIdx.x * blockDim.x + threadIdx.x;
    if (i < E) g_e_cnt[i] = 0;
    if (i < H) g_n_cnt[i] = 0;
    if (i < 192 * 128) {
        int k = i / 128, o = i % 128;
        ((float*)g_W1t)[i] = We1[o * 192 + k];
    }
    if (i < 128 * 128) {
        int k = i / 128, o = i % 128;
        ((float*)g_W2t)[i]  = We2[o * 128 + k];
        ((float*)g_Wpt)[i]  = Wp [o * 128 + k];
        ((float*)g_Wn1t)[i] = Wn1[o * 128 + k];
        ((float*)g_Wn2t)[i] = Wn2[o * 128 + k];
    }
}

// ---------------- build edge-side lists (4 incidences / thread) ---------------
__global__ void __launch_bounds__(256) k_build_e(const int* __restrict__ fg,
                                                 const int* __restrict__ res) {
    int i = blockIdx.x * blockDim.x + threadIdx.x;
    if (i >= NI / 4) return;
    int4 f = ((const int4*)fg)[i];
    int4 r = ((const int4*)res)[i];
    int s;
    s = atomicAdd(&g_e_cnt[r.x], 1); if (s < CAP) g_e_list[r.x * CAP + s] = f.x;
    s = atomicAdd(&g_e_cnt[r.y], 1); if (s < CAP) g_e_list[r.y * CAP + s] = f.y;
    s = atomicAdd(&g_e_cnt[r.z], 1); if (s < CAP) g_e_list[r.z * CAP + s] = f.z;
    s = atomicAdd(&g_e_cnt[r.w], 1); if (s < CAP) g_e_list[r.w * CAP + s] = f.w;
}

// =============================================================================
// Edge MLP (+ fused node-side list build + fused edge gather-mean prologue).
// Blocks [0, NB_BUILD): build g_n_list (runs concurrently under MLP FMA shadow).
// Blocks [NB_BUILD, NB_BUILD+5000): 5 warps, 8 edges/warp as 4 pairs, FFMA2.
// smem rows are 48B (R10-validated layout: 4 pairs + 16B pad).
// =============================================================================
__global__ void __launch_bounds__(160) k_edge_mlp(const float4* __restrict__ xh,
                                                  const float4* __restrict__ attr,
                                                  const float* __restrict__ be1,
                                                  const float* __restrict__ be2,
                                                  const int* __restrict__ fg,
                                                  const int* __restrict__ res) {
    if (blockIdx.x < NB_BUILD) {
        // ---- builder path: node-side lists, 4 incidences / thread ----
        int t = blockIdx.x * 160 + threadIdx.x;
        int base = t * 4;
        if (base + 4 <= NI) {
            int4 f = *(const int4*)(fg + base);
            int4 r = *(const int4*)(res + base);
            int s;
            s = atomicAdd(&g_n_cnt[f.x], 1); if (s < CAP) g_n_list[f.x * CAP + s] = r.x;
            s = atomicAdd(&g_n_cnt[f.y], 1); if (s < CAP) g_n_list[f.y * CAP + s] = r.y;
            s = atomicAdd(&g_n_cnt[f.z], 1); if (s < CAP) g_n_list[f.z * CAP + s] = r.z;
            s = atomicAdd(&g_n_cnt[f.w], 1); if (s < CAP) g_n_list[f.w * CAP + s] = r.w;
        } else {
            for (int i = base; i < NI; i++) {
                int f = fg[i], r = res[i];
                int s = atomicAdd(&g_n_cnt[f], 1);
                if (s < CAP) g_n_list[f * CAP + s] = r;
            }
        }
        return;
    }

    __shared__ __align__(16) float2 s[5][192][6];   // 46080 B (R10 layout)
    int warp = threadIdx.x >> 5, lane = threadIdx.x & 31;
    int e0 = ((blockIdx.x - NB_BUILD) * 5 + warp) * 8;

    // ---- fused gather: mean of member node rows, staged as pairs ----
    #pragma unroll
    for (int jp = 0; jp < 4; jp++) {
        float4 mean[2];
        #pragma unroll
        for (int half = 0; half < 2; half++) {
            int e = e0 + 2 * jp + half;
            int cnt = min(g_e_cnt[e], CAP);
            const int* lst = &g_e_list[e * CAP];
            float4 acc = make_float4(0.f, 0.f, 0.f, 0.f);
            int m = 0;
            for (; m + 4 <= cnt; m += 4) {
                int4 id = *(const int4*)(lst + m);
                float4 v0 = xh[id.x * 32 + lane];
                float4 v1 = xh[id.y * 32 + lane];
                float4 v2 = xh[id.z * 32 + lane];
                float4 v3 = xh[id.w * 32 + lane];
                acc.x += (v0.x + v1.x) + (v2.x + v3.x);
                acc.y += (v0.y + v1.y) + (v2.y + v3.y);
                acc.z += (v0.z + v1.z) + (v2.z + v3.z);
                acc.w += (v0.w + v1.w) + (v2.w + v3.w);
            }
            for (; m < cnt; m++) {
                int id = lst[m];
                float4 v = xh[id * 32 + lane];
                acc.x += v.x; acc.y += v.y; acc.z += v.z; acc.w += v.w;
            }
            float inv = 1.f / (float)max(cnt, 1);
            mean[half] = make_float4(acc.x * inv, acc.y * inv, acc.z * inv, acc.w * inv);
        }
        s[warp][0 * 48 + lane][jp] = make_float2(mean[0].x, mean[1].x);
        s[warp][1 * 48 + lane][jp] = make_float2(mean[0].y, mean[1].y);
        s[warp][2 * 48 + lane][jp] = make_float2(mean[0].z, mean[1].z);
        s[warp][3 * 48 + lane][jp] = make_float2(mean[0].w, mean[1].w);
    }
    // ---- stage attr pairs: rows k=128..191 ----
    #pragma unroll
    for (int jp = 0; jp < 4; jp++) {
        int ea = e0 + 2 * jp, eb = ea + 1;
        if (lane < 16) {
            float4 t0 = attr[ea * 16 + lane];
            float4 t1 = attr[eb * 16 + lane];
            s[warp][0 * 48 + 32 + lane][jp] = make_float2(t0.x, t1.x);
            s[warp][1 * 48 + 32 + lane][jp] = make_float2(t0.y, t1.y);
            s[warp][2 * 48 + 32 + lane][jp] = make_float2(t0.z, t1.z);
            s[warp][3 * 48 + 32 + lane][jp] = make_float2(t0.w, t1.w);
        }
    }
    __syncwarp();

    // ---- GEMM1: [8 x 192] @ [192 x 128] + bias, relu ----
    u64 acc[4][4];
    {
        float4 b = ((const float4*)be1)[lane];
        u64 b0 = dup2(b.x), b1 = dup2(b.y), b2 = dup2(b.z), b3 = dup2(b.w);
        #pragma unroll
        for (int jp = 0; jp < 4; jp++) {
            acc[0][jp] = b0; acc[1][jp] = b1; acc[2][jp] = b2; acc[3][jp] = b3;
        }
    }
    #pragma unroll 2
    for (int kb = 0; kb < 48; kb++) {
        #pragma unroll
        for (int c = 0; c < 4; c++) {
            float4 w = g_W1t[(kb * 4 + c) * 32 + lane];
            u64 w0 = dup2(w.x), w1 = dup2(w.y), w2 = dup2(w.z), w3 = dup2(w.w);
            const float2* row = s[warp][c * 48 + kb];
            ulonglong2 pA = *(const ulonglong2*)(row);       // jp0, jp1
            ulonglong2 pB = *(const ulonglong2*)(row + 2);   // jp2, jp3
            acc[0][0] = ffma2(w0, pA.x, acc[0][0]); acc[1][0] = ffma2(w1, pA.x, acc[1][0]);
            acc[2][0] = ffma2(w2, pA.x, acc[2][0]); acc[3][0] = ffma2(w3, pA.x, acc[3][0]);
            acc[0][1] = ffma2(w0, pA.y, acc[0][1]); acc[1][1] = ffma2(w1, pA.y, acc[1][1]);
            acc[2][1] = ffma2(w2, pA.y, acc[2][1]); acc[3][1] = ffma2(w3, pA.y, acc[3][1]);
            acc[0][2] = ffma2(w0, pB.x, acc[0][2]); acc[1][2] = ffma2(w1, pB.x, acc[1][2]);
            acc[2][2] = ffma2(w2, pB.x, acc[2][2]); acc[3][2] = ffma2(w3, pB.x, acc[3][2]);
            acc[0][3] = ffma2(w0, pB.y, acc[0][3]); acc[1][3] = ffma2(w1, pB.y, acc[1][3]);
            acc[2][3] = ffma2(w2, pB.y, acc[2][3]); acc[3][3] = ffma2(w3, pB.y, acc[3][3]);
        }
    }
    __syncwarp();

    // ---- relu + restage hidden (rows 0..127, G=32) ----
    #pragma unroll
    for (int i = 0; i < 4; i++)
        #pragma unroll
        for (int jp = 0; jp < 4; jp++) {
            float2 v = unpack2(acc[i][jp]);
            s[warp][i * 32 + lane][jp] = make_float2(fmaxf(v.x, 0.f), fmaxf(v.y, 0.f));
        }
    __syncwarp();

    // ---- GEMM2: [8 x 128] @ [128 x 128] + bias ----
    {
        float4 b = ((const float4*)be2)[lane];
        u64 b0 = dup2(b.x), b1 = dup2(b.y), b2 = dup2(b.z), b3 = dup2(b.w);
        #pragma unroll
        for (int jp = 0; jp < 4; jp++) {
            acc[0][jp] = b0; acc[1][jp] = b1; acc[2][jp] = b2; acc[3][jp] = b3;
        }
    }
    #pragma unroll 2
    for (int kb = 0; kb < 32; kb++) {
        #pragma unroll
        for (int c = 0; c < 4; c++) {
            float4 w = g_W2t[(kb * 4 + c) * 32 + lane];
            u64 w0 = dup2(w.x), w1 = dup2(w.y), w2 = dup2(w.z), w3 = dup2(w.w);
            const float2* row = s[warp][c * 32 + kb];
            ulonglong2 pA = *(const ulonglong2*)(row);
            ulonglong2 pB = *(const ulonglong2*)(row + 2);
            acc[0][0] = ffma2(w0, pA.x, acc[0][0]); acc[1][0] = ffma2(w1, pA.x, acc[1][0]);
            acc[2][0] = ffma2(w2, pA.x, acc[2][0]); acc[3][0] = ffma2(w3, pA.x, acc[3][0]);
            acc[0][1] = ffma2(w0, pA.y, acc[0][1]); acc[1][1] = ffma2(w1, pA.y, acc[1][1]);
            acc[2][1] = ffma2(w2, pA.y, acc[2][1]); acc[3][1] = ffma2(w3, pA.y, acc[3][1]);
            acc[0][2] = ffma2(w0, pB.x, acc[0][2]); acc[1][2] = ffma2(w1, pB.x, acc[1][2]);
            acc[2][2] = ffma2(w2, pB.x, acc[2][2]); acc[3][2] = ffma2(w3, pB.x, acc[3][2]);
            acc[0][3] = ffma2(w0, pB.y, acc[0][3]); acc[1][3] = ffma2(w1, pB.y, acc[1][3]);
            acc[2][3] = ffma2(w2, pB.y, acc[2][3]); acc[3][3] = ffma2(w3, pB.y, acc[3][3]);
        }
    }

    // ---- write both edges of each pair ----
    #pragma unroll
    for (int jp = 0; jp < 4; jp++) {
        float2 v0 = unpack2(acc[0][jp]), v1 = unpack2(acc[1][jp]);
        float2 v2 = unpack2(acc[2][jp]), v3 = unpack2(acc[3][jp]);
        g_edge_msg[(e0 + 2 * jp)     * 32 + lane] = make_float4(v0.x, v1.x, v2.x, v3.x);
        g_edge_msg[(e0 + 2 * jp + 1) * 32 + lane] = make_float4(v0.y, v1.y, v2.y, v3.y);
    }
}

// =============================================================================
// Node: fused gather-mean prologue + MLP + residual + relu + layernorm.
// 8 warps/block, 8 nodes/warp (4 pairs). 48KB smem (R10-validated layout).
// =============================================================================
__global__ void __launch_bounds__(256) k_node(const float4* __restrict__ xh,
                                              const float* __restrict__ bp,
                                              const float* __restrict__ bn1,
                                              const float* __restrict__ bn2,
                                              const float4* __restrict__ gamma4,
                                              const float4* __restrict__ beta4,
                                              float4* __restrict__ out) {
    __shared__ __align__(16) float2 s[8][128][6];   // 49152 B
    int warp = threadIdx.x >> 5, lane = threadIdx.x & 31;
    int wg = blockIdx.x * 8 + warp;
    if (wg >= (H / 8)) return;                      // H = 12500 * 8
    int n0 = wg * 8;

    // ---- gather node means directly into smem pair slots ----
    #pragma unroll
    for (int jp = 0; jp < 4; jp++) {
        float4 mean[2];
        #pragma unroll
        for (int half = 0; half < 2; half++) {
            int n = n0 + 2 * jp + half;
            int cnt = min(g_n_cnt[n], CAP);
            const int* lst = &g_n_list[n * CAP];
            float4 acc = make_float4(0.f, 0.f, 0.f, 0.f);
            int m = 0;
            for (; m + 4 <= cnt; m += 4) {
                int4 id = *(const int4*)(lst + m);
                float4 v0 = g_edge_msg[id.x * 32 + lane];
                float4 v1 = g_edge_msg[id.y * 32 + lane];
                float4 v2 = g_edge_msg[id.z * 32 + lane];
                float4 v3 = g_edge_msg[id.w * 32 + lane];
                acc.x += (v0.x + v1.x) + (v2.x + v3.x);
                acc.y += (v0.y + v1.y) + (v2.y + v3.y);
                acc.z += (v0.z + v1.z) + (v2.z + v3.z);
                acc.w += (v0.w + v1.w) + (v2.w + v3.w);
            }
            for (; m < cnt; m++) {
                int id = lst[m];
                float4 v = g_edge_msg[id * 32 + lane];
                acc.x += v.x; acc.y += v.y; acc.z += v.z; acc.w += v.w;
            }
            float inv = 1.f / (float)max(cnt, 1);
            mean[half] = make_float4(acc.x * inv, acc.y * inv, acc.z * inv, acc.w * inv);
        }
        s[warp][0 * 32 + lane][jp] = make_float2(mean[0].x, mean[1].x);
        s[warp][1 * 32 + lane][jp] = make_float2(mean[0].y, mean[1].y);
        s[warp][2 * 32 + lane][jp] = make_float2(mean[0].z, mean[1].z);
        s[warp][3 * 32 + lane][jp] = make_float2(mean[0].w, mean[1].w);
    }
    __syncwarp();

    // ---- t = relu(Wn1 @ m + bn1) ----
    u64 a[4][4];
    {
        float4 b = ((const float4*)bn1)[lane];
        u64 b0 = dup2(b.x), b1 = dup2(b.y), b2 = dup2(b.z), b3 = dup2(b.w);
        #pragma unroll
        for (int jp = 0; jp < 4; jp++) {
            a[0][jp] = b0; a[1][jp] = b1; a[2][jp] = b2; a[3][jp] = b3;
        }
    }
    #pragma unroll 2
    for (int kb = 0; kb < 32; kb++) {
        #pragma unroll
        for (int c = 0; c < 4; c++) {
            float4 w = g_Wn1t[(kb * 4 + c) * 32 + lane];
            u64 w0 = dup2(w.x), w1 = dup2(w.y), w2 = dup2(w.z), w3 = dup2(w.w);
            const float2* row = s[warp][c * 32 + kb];
            ulonglong2 pA = *(const ulonglong2*)(row);
            ulonglong2 pB = *(const ulonglong2*)(row + 2);
            a[0][0] = ffma2(w0, pA.x, a[0][0]); a[1][0] = ffma2(w1, pA.x, a[1][0]);
            a[2][0] = ffma2(w2, pA.x, a[2][0]); a[3][0] = ffma2(w3, pA.x, a[3][0]);
            a[0][1] = ffma2(w0, pA.y, a[0][1]); a[1][1] = ffma2(w1, pA.y, a[1][1]);
            a[2][1] = ffma2(w2, pA.y, a[2][1]); a[3][1] = ffma2(w3, pA.y, a[3][1]);
            a[0][2] = ffma2(w0, pB.x, a[0][2]); a[1][2] = ffma2(w1, pB.x, a[1][2]);
            a[2][2] = ffma2(w2, pB.x, a[2][2]); a[3][2] = ffma2(w3, pB.x, a[3][2]);
            a[0][3] = ffma2(w0, pB.y, a[0][3]); a[1][3] = ffma2(w1, pB.y, a[1][3]);
            a[2][3] = ffma2(w2, pB.y, a[2][3]); a[3][3] = ffma2(w3, pB.y, a[3][3]);
        }
    }
    __syncwarp();
    #pragma unroll
    for (int i = 0; i < 4; i++)
        #pragma unroll
        for (int jp = 0; jp < 4; jp++) {
            float2 v = unpack2(a[i][jp]);
            s[warp][i * 32 + lane][jp] = make_float2(fmaxf(v.x, 0.f), fmaxf(v.y, 0.f));
        }
    __syncwarp();

    // ---- acc = Wn2 @ t + (bn2 + bp) ----
    u64 p[4][4];
    {
        float4 b2 = ((const float4*)bn2)[lane];
        float4 bq = ((const float4*)bp)[lane];
        u64 b0 = dup2(b2.x + bq.x), b1 = dup2(b2.y + bq.y);
        u64 b2d = dup2(b2.z + bq.z), b3 = dup2(b2.w + bq.w);
        #pragma unroll
        for (int jp = 0; jp < 4; jp++) {
            p[0][jp] = b0; p[1][jp] = b1; p[2][jp] = b2d; p[3][jp] = b3;
        }
    }
    #pragma unroll 2
    for (int kb = 0; kb < 32; kb++) {
        #pragma unroll
        for (int c = 0; c < 4; c++) {
            float4 w = g_Wn2t[(kb * 4 + c) * 32 + lane];
            u64 w0 = dup2(w.x), w1 = dup2(w.y), w2 = dup2(w.z), w3 = dup2(w.w);
            const float2* row = s[warp][c * 32 + kb];
            ulonglong2 pA = *(const ulonglong2*)(row);
            ulonglong2 pB = *(const ulonglong2*)(row + 2);
            p[0][0] = ffma2(w0, pA.x, p[0][0]); p[1][0] = ffma2(w1, pA.x, p[1][0]);
            p[2][0] = ffma2(w2, pA.x, p[2][0]); p[3][0] = ffma2(w3, pA.x, p[3][0]);
            p[0][1] = ffma2(w0, pA.y, p[0][1]); p[1][1] = ffma2(w1, pA.y, p[1][1]);
            p[2][1] = ffma2(w2, pA.y, p[2][1]); p[3][1] = ffma2(w3, pA.y, p[3][1]);
            p[0][2] = ffma2(w0, pB.x, p[0][2]); p[1][2] = ffma2(w1, pB.x, p[1][2]);
            p[2][2] = ffma2(w2, pB.x, p[2][2]); p[3][2] = ffma2(w3, pB.x, p[3][2]);
            p[0][3] = ffma2(w0, pB.y, p[0][3]); p[1][3] = ffma2(w1, pB.y, p[1][3]);
            p[2][3] = ffma2(w2, pB.y, p[2][3]); p[3][3] = ffma2(w3, pB.y, p[3][3]);
        }
    }
    __syncwarp();

    // ---- stage x pairs, accumulate Wp @ x into p ----
    #pragma unroll
    for (int jp = 0; jp < 4; jp++) {
        int na = n0 + 2 * jp, nb = na + 1;
        float4 a0 = xh[na * 32 + lane];
        float4 a1 = xh[nb * 32 + lane];
        s[warp][0 * 32 + lane][jp] = make_float2(a0.x, a1.x);
        s[warp][1 * 32 + lane][jp] = make_float2(a0.y, a1.y);
        s[warp][2 * 32 + lane][jp] = make_float2(a0.z, a1.z);
        s[warp][3 * 32 + lane][jp] = make_float2(a0.w, a1.w);
    }
    __syncwarp();
    #pragma unroll 2
    for (int kb = 0; kb < 32; kb++) {
        #pragma unroll
        for (int c = 0; c < 4; c++) {
            float4 w = g_Wpt[(kb * 4 + c) * 32 + lane];
            u64 w0 = dup2(w.x), w1 = dup2(w.y), w2 = dup2(w.z), w3 = dup2(w.w);
            const float2* row = s[warp][c * 32 + kb];
            ulonglong2 pA = *(const ulonglong2*)(row);
            ulonglong2 pB = *(const ulonglong2*)(row + 2);
            p[0][0] = ffma2(w0, pA.x, p[0][0]); p[1][0] = ffma2(w1, pA.x, p[1][0]);
            p[2][0] = ffma2(w2, pA.x, p[2][0]); p[3][0] = ffma2(w3, pA.x, p[3][0]);
            p[0][1] = ffma2(w0, pA.y, p[0][1]); p[1][1] = ffma2(w1, pA.y, p[1][1]);
            p[2][1] = ffma2(w2, pA.y, p[2][1]); p[3][1] = ffma2(w3, pA.y, p[3][1]);
            p[0][2] = ffma2(w0, pB.x, p[0][2]); p[1][2] = ffma2(w1, pB.x, p[1][2]);
            p[2][2] = ffma2(w2, pB.x, p[2][2]); p[3][2] = ffma2(w3, pB.x, p[3][2]);
            p[0][3] = ffma2(w0, pB.y, p[0][3]); p[1][3] = ffma2(w1, pB.y, p[1][3]);
            p[2][3] = ffma2(w2, pB.y, p[2][3]); p[3][3] = ffma2(w3, pB.y, p[3][3]);
        }
    }

    // ---- z = relu(p); layernorm per row (paired, 64-bit shuffles) ----
    float4 gm = gamma4[lane], bt = beta4[lane];
    #pragma unroll
    for (int jp = 0; jp < 4; jp++) {
        u64 z[4];
        #pragma unroll
        for (int i = 0; i < 4; i++) {
            float2 v = unpack2(p[i][jp]);
            z[i] = pack2(fmaxf(v.x, 0.f), fmaxf(v.y, 0.f));
        }
        u64 su = add2(add2(z[0], z[1]), add2(z[2], z[3]));
        u64 qu = ffma2(z[0], z[0], ffma2(z[1], z[1], ffma2(z[2], z[2], mul2(z[3], z[3]))));
        #pragma unroll
        for (int o = 16; o > 0; o >>= 1) {
            su = add2(su, __shfl_xor_sync(0xFFFFFFFFu, su, o));
            qu = add2(qu, __shfl_xor_sync(0xFFFFFFFFu, qu, o));
        }
        float2 sm = unpack2(su), qm = unpack2(qu);
        float mu0 = sm.x * (1.f / 128.f), mu1 = sm.y * (1.f / 128.f);
        float r0 = rsqrtf(qm.x * (1.f / 128.f) - mu0 * mu0 + 1e-5f);
        float r1 = rsqrtf(qm.y * (1.f / 128.f) - mu1 * mu1 + 1e-5f);
        float2 c0 = unpack2(z[0]), c1 = unpack2(z[1]), c2 = unpack2(z[2]), c3 = unpack2(z[3]);
        out[(n0 + 2 * jp) * 32 + lane] =
            make_float4((c0.x - mu0) * r0 * gm.x + bt.x, (c1.x - mu0) * r0 * gm.y + bt.y,
                        (c2.x - mu0) * r0 * gm.z + bt.z, (c3.x - mu0) * r0 * gm.w + bt.w);
        out[(n0 + 2 * jp + 1) * 32 + lane] =
            make_float4((c0.y - mu1) * r1 * gm.x + bt.x, (c1.y - mu1) * r1 * gm.y + bt.y,
                        (c2.y - mu1) * r1 * gm.z + bt.z, (c3.y - mu1) * r1 * gm.w + bt.w);
    }
}

// ---------------- launch -----------------------------------------------------
extern "C" void kernel_launch(void* const* d_in, const int* in_sizes, int n_in,
                              void* d_out, int out_size) {
    const float* x_h   = (const float*)d_in[0];
    const float* attr  = (const float*)d_in[1];
    const float* Wp    = (const float*)d_in[2];
    const float* bp    = (const float*)d_in[3];
    const float* We1   = (const float*)d_in[4];
    const float* be1   = (const float*)d_in[5];
    const float* We2   = (const float*)d_in[6];
    const float* be2   = (const float*)d_in[7];
    const float* Wn1   = (const float*)d_in[8];
    const float* bn1   = (const float*)d_in[9];
    const float* Wn2   = (const float*)d_in[10];
    const float* bn2   = (const float*)d_in[11];
    const float* gamma = (const float*)d_in[12];
    const float* beta  = (const float*)d_in[13];
    const int*   fg    = (const int*)d_in[14];
    const int*   res   = (const int*)d_in[15];

    k_prep_zero<<<(E + 255) / 256, 256>>>(We1, We2, Wp, Wn1, Wn2);
    k_build_e<<<(NI / 4 + 255) / 256, 256>>>(fg, res);
    k_edge_mlp<<<NB_BUILD + 5000, 160>>>((const float4*)x_h, (const float4*)attr,
                                         be1, be2, fg, res);
    k_node<<<1563, 256>>>((const float4*)x_h, bp, bn1, bn2,
                          (const float4*)gamma, (const float4*)beta,
                          (float4*)d_out);
}

// round 16
// speedup vs baseline: 1.0941x; 1.0016x over previous
#include <cuda_runtime.h>
#include <cuda_bf16.h>

#define H  100000
#define E  200000
#define NI 1000000
#define CAP 64
#define NB_BUILD 1563   // builder blocks fused at the front of k_edge_mlp's grid

typedef unsigned long long u64;

// ---------------- scratch (device globals: no allocations allowed) ----------
__device__ int    g_e_cnt[E];
__device__ int    g_n_cnt[H];
__device__ int    g_e_list[E * CAP];    // node ids per edge
__device__ int    g_n_list[H * CAP];    // edge ids per node
__device__ float4 g_edge_msg[E * 32];   // [E][128]

// transposed weights: [k][out] so the k-loop load is lane-coalesced float4
__device__ float4 g_W1t[192 * 32];      // from We1 [128][192]
__device__ float4 g_W2t[128 * 32];      // from We2 [128][128]
__device__ float4 g_Wpt[128 * 32];      // from Wp
__device__ float4 g_Wn1t[128 * 32];
__device__ float4 g_Wn2t[128 * 32];

// ---------------- packed f32x2 helpers ---------------------------------------
__device__ __forceinline__ u64 ffma2(u64 a, u64 b, u64 c) {
    u64 d; asm("fma.rn.f32x2 %0, %1, %2, %3;" : "=l"(d) : "l"(a), "l"(b), "l"(c)); return d;
}
__device__ __forceinline__ u64 add2(u64 a, u64 b) {
    u64 d; asm("add.rn.f32x2 %0, %1, %2;" : "=l"(d) : "l"(a), "l"(b)); return d;
}
__device__ __forceinline__ u64 mul2(u64 a, u64 b) {
    u64 d; asm("mul.rn.f32x2 %0, %1, %2;" : "=l"(d) : "l"(a), "l"(b)); return d;
}
__device__ __forceinline__ u64 dup2(float f) {
    u64 d; asm("mov.b64 %0, {%1, %1};" : "=l"(d) : "f"(f)); return d;
}
__device__ __forceinline__ u64 pack2(float x, float y) {
    u64 d; asm("mov.b64 %0, {%1, %2};" : "=l"(d) : "f"(x), "f"(y)); return d;
}
__device__ __forceinline__ float2 unpack2(u64 v) {
    float2 r; asm("mov.b64 {%0, %1}, %2;" : "=f"(r.x), "=f"(r.y) : "l"(v)); return r;
}

// ---------------- prep: zero counters + transpose weights --------------------
__global__ void k_prep_zero(const float* __restrict__ We1, const float* __restrict__ We2,
                            const float* __restrict__ Wp,  const float* __restrict__ Wn1,
                            const float* __restrict__ Wn2) {
    int i = blockIdx.x * blockDim.x + threadIdx.x;
    if (i < E) g_e_cnt[i] = 0;
    if (i < H) g_n_cnt[i] = 0;
    if (i < 192 * 128) {
        int k = i / 128, o = i % 128;
        ((float*)g_W1t)[i] = We1[o * 192 + k];
    }
    if (i < 128 * 128) {
        int k = i / 128, o = i % 128;
        ((float*)g_W2t)[i]  = We2[o * 128 + k];
        ((float*)g_Wpt)[i]  = Wp [o * 128 + k];
        ((float*)g_Wn1t)[i] = Wn1[o * 128 + k];
        ((float*)g_Wn2t)[i] = Wn2[o * 128 + k];
    }
}

// ---------------- build edge-side lists (4 incidences / thread) ---------------
__global__ void __launch_bounds__(256) k_build_e(const int* __restrict__ fg,
                                                 const int* __restrict__ res) {
    int i = blockIdx.x * blockDim.x + threadIdx.x;
    if (i >= NI / 4) return;
    int4 f = ((const int4*)fg)[i];
    int4 r = ((const int4*)res)[i];
    int s;
    s = atomicAdd(&g_e_cnt[r.x], 1); if (s < CAP) g_e_list[r.x * CAP + s] = f.x;
    s = atomicAdd(&g_e_cnt[r.y], 1); if (s < CAP) g_e_list[r.y * CAP + s] = f.y;
    s = atomicAdd(&g_e_cnt[r.z], 1); if (s < CAP) g_e_list[r.z * CAP + s] = f.z;
    s = atomicAdd(&g_e_cnt[r.w], 1); if (s < CAP) g_e_list[r.w * CAP + s] = f.w;
}

// =============================================================================
// Edge MLP (+ fused node-side list build + fused edge gather-mean prologue).
// Blocks [0, NB_BUILD): build g_n_list (runs concurrently under MLP FMA shadow).
// Blocks [NB_BUILD, NB_BUILD+5000): 5 warps, 8 edges/warp as 4 pairs, FFMA2.
// smem rows are 48B (R10-validated layout: 4 pairs + 16B pad).
// =============================================================================
__global__ void __launch_bounds__(160) k_edge_mlp(const float4* __restrict__ xh,
                                                  const float4* __restrict__ attr,
                                                  const float* __restrict__ be1,
                                                  const float* __restrict__ be2,
                                                  const int* __restrict__ fg,
                                                  const int* __restrict__ res) {
    if (blockIdx.x < NB_BUILD) {
        // ---- builder path: node-side lists, 4 incidences / thread ----
        int t = blockIdx.x * 160 + threadIdx.x;
        int base = t * 4;
        if (base + 4 <= NI) {
            int4 f = *(const int4*)(fg + base);
            int4 r = *(const int4*)(res + base);
            int s;
            s = atomicAdd(&g_n_cnt[f.x], 1); if (s < CAP) g_n_list[f.x * CAP + s] = r.x;
            s = atomicAdd(&g_n_cnt[f.y], 1); if (s < CAP) g_n_list[f.y * CAP + s] = r.y;
            s = atomicAdd(&g_n_cnt[f.z], 1); if (s < CAP) g_n_list[f.z * CAP + s] = r.z;
            s = atomicAdd(&g_n_cnt[f.w], 1); if (s < CAP) g_n_list[f.w * CAP + s] = r.w;
        } else {
            for (int i = base; i < NI; i++) {
                int f = fg[i], r = res[i];
                int s = atomicAdd(&g_n_cnt[f], 1);
                if (s < CAP) g_n_list[f * CAP + s] = r;
            }
        }
        return;
    }

    __shared__ __align__(16) float2 s[5][192][6];   // 46080 B (R10 layout)
    int warp = threadIdx.x >> 5, lane = threadIdx.x & 31;
    int e0 = ((blockIdx.x - NB_BUILD) * 5 + warp) * 8;

    // ---- fused gather: mean of member node rows, staged as pairs ----
    #pragma unroll
    for (int jp = 0; jp < 4; jp++) {
        float4 mean[2];
        #pragma unroll
        for (int half = 0; half < 2; half++) {
            int e = e0 + 2 * jp + half;
            int cnt = min(g_e_cnt[e], CAP);
            const int* lst = &g_e_list[e * CAP];
            float4 acc = make_float4(0.f, 0.f, 0.f, 0.f);
            int m = 0;
            for (; m + 4 <= cnt; m += 4) {
                int4 id = *(const int4*)(lst + m);
                float4 v0 = xh[id.x * 32 + lane];
                float4 v1 = xh[id.y * 32 + lane];
                float4 v2 = xh[id.z * 32 + lane];
                float4 v3 = xh[id.w * 32 + lane];
                acc.x += (v0.x + v1.x) + (v2.x + v3.x);
                acc.y += (v0.y + v1.y) + (v2.y + v3.y);
                acc.z += (v0.z + v1.z) + (v2.z + v3.z);
                acc.w += (v0.w + v1.w) + (v2.w + v3.w);
            }
            for (; m < cnt; m++) {
                int id = lst[m];
                float4 v = xh[id * 32 + lane];
                acc.x += v.x; acc.y += v.y; acc.z += v.z; acc.w += v.w;
            }
            float inv = 1.f / (float)max(cnt, 1);
            mean[half] = make_float4(acc.x * inv, acc.y * inv, acc.z * inv, acc.w * inv);
        }
        s[warp][0 * 48 + lane][jp] = make_float2(mean[0].x, mean[1].x);
        s[warp][1 * 48 + lane][jp] = make_float2(mean[0].y, mean[1].y);
        s[warp][2 * 48 + lane][jp] = make_float2(mean[0].z, mean[1].z);
        s[warp][3 * 48 + lane][jp] = make_float2(mean[0].w, mean[1].w);
    }
    // ---- stage attr pairs: rows k=128..191 ----
    #pragma unroll
    for (int jp = 0; jp < 4; jp++) {
        int ea = e0 + 2 * jp, eb = ea + 1;
        if (lane < 16) {
            float4 t0 = attr[ea * 16 + lane];
            float4 t1 = attr[eb * 16 + lane];
            s[warp][0 * 48 + 32 + lane][jp] = make_float2(t0.x, t1.x);
            s[warp][1 * 48 + 32 + lane][jp] = make_float2(t0.y, t1.y);
            s[warp][2 * 48 + 32 + lane][jp] = make_float2(t0.z, t1.z);
            s[warp][3 * 48 + 32 + lane][jp] = make_float2(t0.w, t1.w);
        }
    }
    __syncwarp();

    // ---- GEMM1: [8 x 192] @ [192 x 128] + bias, relu ----
    u64 acc[4][4];
    {
        float4 b = ((const float4*)be1)[lane];
        u64 b0 = dup2(b.x), b1 = dup2(b.y), b2 = dup2(b.z), b3 = dup2(b.w);
        #pragma unroll
        for (int jp = 0; jp < 4; jp++) {
            acc[0][jp] = b0; acc[1][jp] = b1; acc[2][jp] = b2; acc[3][jp] = b3;
        }
    }
    #pragma unroll 2
    for (int kb = 0; kb < 48; kb++) {
        #pragma unroll
        for (int c = 0; c < 4; c++) {
            float4 w = g_W1t[(kb * 4 + c) * 32 + lane];
            u64 w0 = dup2(w.x), w1 = dup2(w.y), w2 = dup2(w.z), w3 = dup2(w.w);
            const float2* row = s[warp][c * 48 + kb];
            ulonglong2 pA = *(const ulonglong2*)(row);       // jp0, jp1
            ulonglong2 pB = *(const ulonglong2*)(row + 2);   // jp2, jp3
            acc[0][0] = ffma2(w0, pA.x, acc[0][0]); acc[1][0] = ffma2(w1, pA.x, acc[1][0]);
            acc[2][0] = ffma2(w2, pA.x, acc[2][0]); acc[3][0] = ffma2(w3, pA.x, acc[3][0]);
            acc[0][1] = ffma2(w0, pA.y, acc[0][1]); acc[1][1] = ffma2(w1, pA.y, acc[1][1]);
            acc[2][1] = ffma2(w2, pA.y, acc[2][1]); acc[3][1] = ffma2(w3, pA.y, acc[3][1]);
            acc[0][2] = ffma2(w0, pB.x, acc[0][2]); acc[1][2] = ffma2(w1, pB.x, acc[1][2]);
            acc[2][2] = ffma2(w2, pB.x, acc[2][2]); acc[3][2] = ffma2(w3, pB.x, acc[3][2]);
            acc[0][3] = ffma2(w0, pB.y, acc[0][3]); acc[1][3] = ffma2(w1, pB.y, acc[1][3]);
            acc[2][3] = ffma2(w2, pB.y, acc[2][3]); acc[3][3] = ffma2(w3, pB.y, acc[3][3]);
        }
    }
    __syncwarp();

    // ---- relu + restage hidden (rows 0..127, G=32) ----
    #pragma unroll
    for (int i = 0; i < 4; i++)
        #pragma unroll
        for (int jp = 0; jp < 4; jp++) {
            float2 v = unpack2(acc[i][jp]);
            s[warp][i * 32 + lane][jp] = make_float2(fmaxf(v.x, 0.f), fmaxf(v.y, 0.f));
        }
    __syncwarp();

    // ---- GEMM2: [8 x 128] @ [128 x 128] + bias ----
    {
        float4 b = ((const float4*)be2)[lane];
        u64 b0 = dup2(b.x), b1 = dup2(b.y), b2 = dup2(b.z), b3 = dup2(b.w);
        #pragma unroll
        for (int jp = 0; jp < 4; jp++) {
            acc[0][jp] = b0; acc[1][jp] = b1; acc[2][jp] = b2; acc[3][jp] = b3;
        }
    }
    #pragma unroll 2
    for (int kb = 0; kb < 32; kb++) {
        #pragma unroll
        for (int c = 0; c < 4; c++) {
            float4 w = g_W2t[(kb * 4 + c) * 32 + lane];
            u64 w0 = dup2(w.x), w1 = dup2(w.y), w2 = dup2(w.z), w3 = dup2(w.w);
            const float2* row = s[warp][c * 32 + kb];
            ulonglong2 pA = *(const ulonglong2*)(row);
            ulonglong2 pB = *(const ulonglong2*)(row + 2);
            acc[0][0] = ffma2(w0, pA.x, acc[0][0]); acc[1][0] = ffma2(w1, pA.x, acc[1][0]);
            acc[2][0] = ffma2(w2, pA.x, acc[2][0]); acc[3][0] = ffma2(w3, pA.x, acc[3][0]);
            acc[0][1] = ffma2(w0, pA.y, acc[0][1]); acc[1][1] = ffma2(w1, pA.y, acc[1][1]);
            acc[2][1] = ffma2(w2, pA.y, acc[2][1]); acc[3][1] = ffma2(w3, pA.y, acc[3][1]);
            acc[0][2] = ffma2(w0, pB.x, acc[0][2]); acc[1][2] = ffma2(w1, pB.x, acc[1][2]);
            acc[2][2] = ffma2(w2, pB.x, acc[2][2]); acc[3][2] = ffma2(w3, pB.x, acc[3][2]);
            acc[0][3] = ffma2(w0, pB.y, acc[0][3]); acc[1][3] = ffma2(w1, pB.y, acc[1][3]);
            acc[2][3] = ffma2(w2, pB.y, acc[2][3]); acc[3][3] = ffma2(w3, pB.y, acc[3][3]);
        }
    }

    // ---- write both edges of each pair ----
    #pragma unroll
    for (int jp = 0; jp < 4; jp++) {
        float2 v0 = unpack2(acc[0][jp]), v1 = unpack2(acc[1][jp]);
        float2 v2 = unpack2(acc[2][jp]), v3 = unpack2(acc[3][jp]);
        g_edge_msg[(e0 + 2 * jp)     * 32 + lane] = make_float4(v0.x, v1.x, v2.x, v3.x);
        g_edge_msg[(e0 + 2 * jp + 1) * 32 + lane] = make_float4(v0.y, v1.y, v2.y, v3.y);
    }
}

// =============================================================================
// Node: fused gather-mean prologue + MLP + residual + relu + layernorm.
// 4 warps/block (128 thr), 8 nodes/warp (4 pairs), grid 3125 (H/32 exact).
// 24.6KB smem -> ~9 blocks/SM: gather-latency phases of some blocks overlap
// FMA phases of others (phase diversity), vs 4 near-lockstep blocks before.
// Per-warp code identical to the R10/R13-validated version.
// =============================================================================
__global__ void __launch_bounds__(128) k_node(const float4* __restrict__ xh,
                                              const float* __restrict__ bp,
                                              const float* __restrict__ bn1,
                                              const float* __restrict__ bn2,
                                              const float4* __restrict__ gamma4,
                                              const float4* __restrict__ beta4,
                                              float4* __restrict__ out) {
    __shared__ __align__(16) float2 s[4][128][6];   // 24576 B
    int warp = threadIdx.x >> 5, lane = threadIdx.x & 31;
    int wg = blockIdx.x * 4 + warp;
    if (wg >= (H / 8)) return;                      // H = 12500 * 8
    int n0 = wg * 8;

    // ---- gather node means directly into smem pair slots ----
    #pragma unroll
    for (int jp = 0; jp < 4; jp++) {
        float4 mean[2];
        #pragma unroll
        for (int half = 0; half < 2; half++) {
            int n = n0 + 2 * jp + half;
            int cnt = min(g_n_cnt[n], CAP);
            const int* lst = &g_n_list[n * CAP];
            float4 acc = make_float4(0.f, 0.f, 0.f, 0.f);
            int m = 0;
            for (; m + 4 <= cnt; m += 4) {
                int4 id = *(const int4*)(lst + m);
                float4 v0 = g_edge_msg[id.x * 32 + lane];
                float4 v1 = g_edge_msg[id.y * 32 + lane];
                float4 v2 = g_edge_msg[id.z * 32 + lane];
                float4 v3 = g_edge_msg[id.w * 32 + lane];
                acc.x += (v0.x + v1.x) + (v2.x + v3.x);
                acc.y += (v0.y + v1.y) + (v2.y + v3.y);
                acc.z += (v0.z + v1.z) + (v2.z + v3.z);
                acc.w += (v0.w + v1.w) + (v2.w + v3.w);
            }
            for (; m < cnt; m++) {
                int id = lst[m];
                float4 v = g_edge_msg[id * 32 + lane];
                acc.x += v.x; acc.y += v.y; acc.z += v.z; acc.w += v.w;
            }
            float inv = 1.f / (float)max(cnt, 1);
            mean[half] = make_float4(acc.x * inv, acc.y * inv, acc.z * inv, acc.w * inv);
        }
        s[warp][0 * 32 + lane][jp] = make_float2(mean[0].x, mean[1].x);
        s[warp][1 * 32 + lane][jp] = make_float2(mean[0].y, mean[1].y);
        s[warp][2 * 32 + lane][jp] = make_float2(mean[0].z, mean[1].z);
        s[warp][3 * 32 + lane][jp] = make_float2(mean[0].w, mean[1].w);
    }
    __syncwarp();

    // ---- t = relu(Wn1 @ m + bn1) ----
    u64 a[4][4];
    {
        float4 b = ((const float4*)bn1)[lane];
        u64 b0 = dup2(b.x), b1 = dup2(b.y), b2 = dup2(b.z), b3 = dup2(b.w);
        #pragma unroll
        for (int jp = 0; jp < 4; jp++) {
            a[0][jp] = b0; a[1][jp] = b1; a[2][jp] = b2; a[3][jp] = b3;
        }
    }
    #pragma unroll 2
    for (int kb = 0; kb < 32; kb++) {
        #pragma unroll
        for (int c = 0; c < 4; c++) {
            float4 w = g_Wn1t[(kb * 4 + c) * 32 + lane];
            u64 w0 = dup2(w.x), w1 = dup2(w.y), w2 = dup2(w.z), w3 = dup2(w.w);
            const float2* row = s[warp][c * 32 + kb];
            ulonglong2 pA = *(const ulonglong2*)(row);
            ulonglong2 pB = *(const ulonglong2*)(row + 2);
            a[0][0] = ffma2(w0, pA.x, a[0][0]); a[1][0] = ffma2(w1, pA.x, a[1][0]);
            a[2][0] = ffma2(w2, pA.x, a[2][0]); a[3][0] = ffma2(w3, pA.x, a[3][0]);
            a[0][1] = ffma2(w0, pA.y, a[0][1]); a[1][1] = ffma2(w1, pA.y, a[1][1]);
            a[2][1] = ffma2(w2, pA.y, a[2][1]); a[3][1] = ffma2(w3, pA.y, a[3][1]);
            a[0][2] = ffma2(w0, pB.x, a[0][2]); a[1][2] = ffma2(w1, pB.x, a[1][2]);
            a[2][2] = ffma2(w2, pB.x, a[2][2]); a[3][2] = ffma2(w3, pB.x, a[3][2]);
            a[0][3] = ffma2(w0, pB.y, a[0][3]); a[1][3] = ffma2(w1, pB.y, a[1][3]);
            a[2][3] = ffma2(w2, pB.y, a[2][3]); a[3][3] = ffma2(w3, pB.y, a[3][3]);
        }
    }
    __syncwarp();
    #pragma unroll
    for (int i = 0; i < 4; i++)
        #pragma unroll
        for (int jp = 0; jp < 4; jp++) {
            float2 v = unpack2(a[i][jp]);
            s[warp][i * 32 + lane][jp] = make_float2(fmaxf(v.x, 0.f), fmaxf(v.y, 0.f));
        }
    __syncwarp();

    // ---- acc = Wn2 @ t + (bn2 + bp) ----
    u64 p[4][4];
    {
        float4 b2 = ((const float4*)bn2)[lane];
        float4 bq = ((const float4*)bp)[lane];
        u64 b0 = dup2(b2.x + bq.x), b1 = dup2(b2.y + bq.y);
        u64 b2d = dup2(b2.z + bq.z), b3 = dup2(b2.w + bq.w);
        #pragma unroll
        for (int jp = 0; jp < 4; jp++) {
            p[0][jp] = b0; p[1][jp] = b1; p[2][jp] = b2d; p[3][jp] = b3;
        }
    }
    #pragma unroll 2
    for (int kb = 0; kb < 32; kb++) {
        #pragma unroll
        for (int c = 0; c < 4; c++) {
            float4 w = g_Wn2t[(kb * 4 + c) * 32 + lane];
            u64 w0 = dup2(w.x), w1 = dup2(w.y), w2 = dup2(w.z), w3 = dup2(w.w);
            const float2* row = s[warp][c * 32 + kb];
            ulonglong2 pA = *(const ulonglong2*)(row);
            ulonglong2 pB = *(const ulonglong2*)(row + 2);
            p[0][0] = ffma2(w0, pA.x, p[0][0]); p[1][0] = ffma2(w1, pA.x, p[1][0]);
            p[2][0] = ffma2(w2, pA.x, p[2][0]); p[3][0] = ffma2(w3, pA.x, p[3][0]);
            p[0][1] = ffma2(w0, pA.y, p[0][1]); p[1][1] = ffma2(w1, pA.y, p[1][1]);
            p[2][1] = ffma2(w2, pA.y, p[2][1]); p[3][1] = ffma2(w3, pA.y, p[3][1]);
            p[0][2] = ffma2(w0, pB.x, p[0][2]); p[1][2] = ffma2(w1, pB.x, p[1][2]);
            p[2][2] = ffma2(w2, pB.x, p[2][2]); p[3][2] = ffma2(w3, pB.x, p[3][2]);
            p[0][3] = ffma2(w0, pB.y, p[0][3]); p[1][3] = ffma2(w1, pB.y, p[1][3]);
            p[2][3] = ffma2(w2, pB.y, p[2][3]); p[3][3] = ffma2(w3, pB.y, p[3][3]);
        }
    }
    __syncwarp();

    // ---- stage x pairs, accumulate Wp @ x into p ----
    #pragma unroll
    for (int jp = 0; jp < 4; jp++) {
        int na = n0 + 2 * jp, nb = na + 1;
        float4 a0 = xh[na * 32 + lane];
        float4 a1 = xh[nb * 32 + lane];
        s[warp][0 * 32 + lane][jp] = make_float2(a0.x, a1.x);
        s[warp][1 * 32 + lane][jp] = make_float2(a0.y, a1.y);
        s[warp][2 * 32 + lane][jp] = make_float2(a0.z, a1.z);
        s[warp][3 * 32 + lane][jp] = make_float2(a0.w, a1.w);
    }
    __syncwarp();
    #pragma unroll 2
    for (int kb = 0; kb < 32; kb++) {
        #pragma unroll
        for (int c = 0; c < 4; c++) {
            float4 w = g_Wpt[(kb * 4 + c) * 32 + lane];
            u64 w0 = dup2(w.x), w1 = dup2(w.y), w2 = dup2(w.z), w3 = dup2(w.w);
            const float2* row = s[warp][c * 32 + kb];
            ulonglong2 pA = *(const ulonglong2*)(row);
            ulonglong2 pB = *(const ulonglong2*)(row + 2);
            p[0][0] = ffma2(w0, pA.x, p[0][0]); p[1][0] = ffma2(w1, pA.x, p[1][0]);
            p[2][0] = ffma2(w2, pA.x, p[2][0]); p[3][0] = ffma2(w3, pA.x, p[3][0]);
            p[0][1] = ffma2(w0, pA.y, p[0][1]); p[1][1] = ffma2(w1, pA.y, p[1][1]);
            p[2][1] = ffma2(w2, pA.y, p[2][1]); p[3][1] = ffma2(w3, pA.y, p[3][1]);
            p[0][2] = ffma2(w0, pB.x, p[0][2]); p[1][2] = ffma2(w1, pB.x, p[1][2]);
            p[2][2] = ffma2(w2, pB.x, p[2][2]); p[3][2] = ffma2(w3, pB.x, p[3][2]);
            p[0][3] = ffma2(w0, pB.y, p[0][3]); p[1][3] = ffma2(w1, pB.y, p[1][3]);
            p[2][3] = ffma2(w2, pB.y, p[2][3]); p[3][3] = ffma2(w3, pB.y, p[3][3]);
        }
    }

    // ---- z = relu(p); layernorm per row (paired, 64-bit shuffles) ----
    float4 gm = gamma4[lane], bt = beta4[lane];
    #pragma unroll
    for (int jp = 0; jp < 4; jp++) {
        u64 z[4];
        #pragma unroll
        for (int i = 0; i < 4; i++) {
            float2 v = unpack2(p[i][jp]);
            z[i] = pack2(fmaxf(v.x, 0.f), fmaxf(v.y, 0.f));
        }
        u64 su = add2(add2(z[0], z[1]), add2(z[2], z[3]));
        u64 qu = ffma2(z[0], z[0], ffma2(z[1], z[1], ffma2(z[2], z[2], mul2(z[3], z[3]))));
        #pragma unroll
        for (int o = 16; o > 0; o >>= 1) {
            su = add2(su, __shfl_xor_sync(0xFFFFFFFFu, su, o));
            qu = add2(qu, __shfl_xor_sync(0xFFFFFFFFu, qu, o));
        }
        float2 sm = unpack2(su), qm = unpack2(qu);
        float mu0 = sm.x * (1.f / 128.f), mu1 = sm.y * (1.f / 128.f);
        float r0 = rsqrtf(qm.x * (1.f / 128.f) - mu0 * mu0 + 1e-5f);
        float r1 = rsqrtf(qm.y * (1.f / 128.f) - mu1 * mu1 + 1e-5f);
        float2 c0 = unpack2(z[0]), c1 = unpack2(z[1]), c2 = unpack2(z[2]), c3 = unpack2(z[3]);
        out[(n0 + 2 * jp) * 32 + lane] =
            make_float4((c0.x - mu0) * r0 * gm.x + bt.x, (c1.x - mu0) * r0 * gm.y + bt.y,
                        (c2.x - mu0) * r0 * gm.z + bt.z, (c3.x - mu0) * r0 * gm.w + bt.w);
        out[(n0 + 2 * jp + 1) * 32 + lane] =
            make_float4((c0.y - mu1) * r1 * gm.x + bt.x, (c1.y - mu1) * r1 * gm.y + bt.y,
                        (c2.y - mu1) * r1 * gm.z + bt.z, (c3.y - mu1) * r1 * gm.w + bt.w);
    }
}

// ---------------- launch -----------------------------------------------------
extern "C" void kernel_launch(void* const* d_in, const int* in_sizes, int n_in,
                              void* d_out, int out_size) {
    const float* x_h   = (const float*)d_in[0];
    const float* attr  = (const float*)d_in[1];
    const float* Wp    = (const float*)d_in[2];
    const float* bp    = (const float*)d_in[3];
    const float* We1   = (const float*)d_in[4];
    const float* be1   = (const float*)d_in[5];
    const float* We2   = (const float*)d_in[6];
    const float* be2   = (const float*)d_in[7];
    const float* Wn1   = (const float*)d_in[8];
    const float* bn1   = (const float*)d_in[9];
    const float* Wn2   = (const float*)d_in[10];
    const float* bn2   = (const float*)d_in[11];
    const float* gamma = (const float*)d_in[12];
    const float* beta  = (const float*)d_in[13];
    const int*   fg    = (const int*)d_in[14];
    const int*   res   = (const int*)d_in[15];

    k_prep_zero<<<(E + 255) / 256, 256>>>(We1, We2, Wp, Wn1, Wn2);
    k_build_e<<<(NI / 4 + 255) / 256, 256>>>(fg, res);
    k_edge_mlp<<<NB_BUILD + 5000, 160>>>((const float4*)x_h, (const float4*)attr,
                                         be1, be2, fg, res);
    k_node<<<3125, 128>>>((const float4*)x_h, bp, bn1, bn2,
                          (const float4*)gamma, (const float4*)beta,
                          (float4*)d_out);
}